// round 4
// baseline (speedup 1.0000x reference)
#include <cuda_runtime.h>
#include <cstdint>

#define TILE_M   128
#define LDA      132          // 128 + 4 floats pad -> conflict-free fragment LDS
#define NTHREADS 256
#define RES_KS   12           // K-steps of W kept resident in registers (of 16)

__device__ int g_idx_is64;

// Index dtype sniffing: int64 indices (< 2^31, non-negative) have all-zero high
// words; int32 index data at odd word positions is ~never all-zero for 64 samples.
__global__ void detect_idx_kernel(const unsigned int* __restrict__ w) {
    if (threadIdx.x == 0) {
        int is64 = 1;
        for (int i = 0; i < 64; i++)
            if (w[2 * i + 1] != 0u) { is64 = 0; break; }
        g_idx_is64 = is64;
    }
}

__device__ __forceinline__ void cp16(float* dst, const float* src) {
    uint32_t d = (uint32_t)__cvta_generic_to_shared(dst);
    asm volatile("cp.async.cg.shared.global [%0], [%1], 16;\n" :: "r"(d), "l"(src));
}

__device__ __forceinline__ uint32_t f2tf32(float v) {
    uint32_t u;
    asm("cvt.rna.tf32.f32 %0, %1;" : "=r"(u) : "f"(v));
    return u;
}

__device__ __forceinline__ void mma_tf32(float c[4], uint32_t a0, uint32_t a1,
                                         uint32_t a2, uint32_t a3,
                                         uint32_t b0, uint32_t b1) {
    asm volatile(
        "mma.sync.aligned.m16n8k8.row.col.f32.tf32.tf32.f32 "
        "{%0,%1,%2,%3}, {%4,%5,%6,%7}, {%8,%9}, {%0,%1,%2,%3};\n"
        : "+f"(c[0]), "+f"(c[1]), "+f"(c[2]), "+f"(c[3])
        : "r"(a0), "r"(a1), "r"(a2), "r"(a3), "r"(b0), "r"(b1));
}

__global__ void __launch_bounds__(NTHREADS, 1)
edge_encoder_kernel(const float* __restrict__ x,
                    const float* __restrict__ ea,
                    const void* __restrict__ idx,
                    const float* __restrict__ Wg,
                    const float* __restrict__ bg,
                    float* __restrict__ out,
                    int E, int ntiles) {
    extern __shared__ float smem[];
    float* As = smem;                       // 2 stages * 128 * LDA
    float* Ws = smem + 2 * TILE_M * LDA;    // 128 * LDA  (TF32-rounded W, [n][k])
    float* Bs = Ws + 128 * LDA;             // 128 bias

    const int tid  = threadIdx.x;
    const int lane = tid & 31;
    const int warp = tid >> 5;
    const int g    = lane >> 2;   // groupID 0..7
    const int tig  = lane & 3;    // thread-in-group 0..3
    const int wm   = warp >> 2;   // 0..1  (64-row slab)
    const int wn   = warp & 3;    // 0..3  (32-col slab)
    const int is64 = g_idx_is64;

    // Stage W (pre-rounded to TF32, [n][k] with LDA pad) and bias once per CTA.
    for (int i = tid; i < 128 * 128; i += NTHREADS) {
        int r = i >> 7, c = i & 127;
        Ws[r * LDA + c] = __uint_as_float(f2tf32(Wg[i]));
    }
    if (tid < 128) Bs[tid] = bg[tid];

    // Gather: thread owns one (row, half). half0 -> x[row[e]], half1 -> edge_attr[e].
    const int rowi = tid >> 1;
    const int half = tid & 1;
    auto issue = [&](int stage, long tile) {
        long e  = tile * TILE_M + rowi;
        long ec = e < E ? e : (long)(E - 1);
        const float* src;
        if (half == 0) {
            long r = is64 ? (long)((const long long*)idx)[ec]
                          : (long)((const int*)idx)[ec];
            src = x + (r << 6);
        } else {
            src = ea + (ec << 6);
        }
        float* dst = As + stage * (TILE_M * LDA) + rowi * LDA + half * 64;
        #pragma unroll
        for (int q = 0; q < 16; q++) cp16(dst + q * 4, src + q * 4);
    };

    long tile0 = blockIdx.x;
    if (tile0 < ntiles) issue(0, tile0);
    asm volatile("cp.async.commit_group;\n");
    __syncthreads();   // Ws / Bs visible

    // ---- Hoist W fragments for K-steps [0, RES_KS) into registers ----
    // B fragment for (ks, nn): element (col = wn*32 + nn*8 + g, k = 8*ks + tig / +4)
    uint32_t breg[RES_KS][4][2];
    {
        const float* Bp = Ws + (wn * 32 + g) * LDA + tig;
        #pragma unroll
        for (int ks = 0; ks < RES_KS; ks++)
            #pragma unroll
            for (int nn = 0; nn < 4; nn++) {
                const float* bp = Bp + nn * 8 * LDA + ks * 8;
                breg[ks][nn][0] = __float_as_uint(bp[0]);
                breg[ks][nn][1] = __float_as_uint(bp[4]);
            }
    }
    // Hoisted bias (cols wn*32 + nn*8 + 2*tig)
    float2 bb[4];
    #pragma unroll
    for (int nn = 0; nn < 4; nn++) {
        int col = wn * 32 + nn * 8 + 2 * tig;
        bb[nn] = make_float2(Bs[col], Bs[col + 1]);
    }

    int s = 0;
    for (long tile = tile0; tile < ntiles; tile += gridDim.x, s ^= 1) {
        long nxt = tile + gridDim.x;
        if (nxt < ntiles) issue(s ^ 1, nxt);
        asm volatile("cp.async.commit_group;\n");
        asm volatile("cp.async.wait_group 1;\n");   // current stage landed
        __syncthreads();

        const float* A0 = As + s * (TILE_M * LDA);

        float c[4][4][4];   // [m16-block][n8-block][frag]
        #pragma unroll
        for (int mb = 0; mb < 4; mb++)
            #pragma unroll
            for (int nn = 0; nn < 4; nn++)
                #pragma unroll
                for (int q = 0; q < 4; q++) c[mb][nn][q] = 0.f;

        const float* Ap = A0 + (wm * 64 + g) * LDA + tig;
        const float* Bp = Ws + (wn * 32 + g) * LDA + tig;

        #pragma unroll
        for (int ks = 0; ks < 16; ks++) {
            uint32_t a[4][4];
            #pragma unroll
            for (int mb = 0; mb < 4; mb++) {
                const float* ap = Ap + mb * 16 * LDA + ks * 8;
                a[mb][0] = f2tf32(ap[0]);
                a[mb][1] = f2tf32(ap[8 * LDA]);
                a[mb][2] = f2tf32(ap[4]);
                a[mb][3] = f2tf32(ap[8 * LDA + 4]);
            }
            uint32_t bf[4][2];
            if (ks < RES_KS) {
                #pragma unroll
                for (int nn = 0; nn < 4; nn++) {
                    bf[nn][0] = breg[ks][nn][0];
                    bf[nn][1] = breg[ks][nn][1];
                }
            } else {
                #pragma unroll
                for (int nn = 0; nn < 4; nn++) {
                    const float* bp = Bp + nn * 8 * LDA + ks * 8;
                    bf[nn][0] = __float_as_uint(bp[0]);
                    bf[nn][1] = __float_as_uint(bp[4]);
                }
            }
            #pragma unroll
            for (int mb = 0; mb < 4; mb++)
                #pragma unroll
                for (int nn = 0; nn < 4; nn++)
                    mma_tf32(c[mb][nn], a[mb][0], a[mb][1], a[mb][2], a[mb][3],
                             bf[nn][0], bf[nn][1]);
        }

        // Epilogue: bias + relu + float2 stores.
        #pragma unroll
        for (int mb = 0; mb < 4; mb++) {
            long e0 = tile * TILE_M + wm * 64 + mb * 16 + g;
            #pragma unroll
            for (int hh = 0; hh < 2; hh++) {
                long e = e0 + hh * 8;
                if (e < E) {
                    float* orow = out + e * 128 + wn * 32 + 2 * tig;
                    #pragma unroll
                    for (int nn = 0; nn < 4; nn++) {
                        float v0 = fmaxf(c[mb][nn][2 * hh + 0] + bb[nn].x, 0.f);
                        float v1 = fmaxf(c[mb][nn][2 * hh + 1] + bb[nn].y, 0.f);
                        *(float2*)(orow + nn * 8) = make_float2(v0, v1);
                    }
                }
            }
        }
        __syncthreads();  // protect stage s before refill next iteration
    }
}

extern "C" void kernel_launch(void* const* d_in, const int* in_sizes, int n_in,
                              void* d_out, int out_size) {
    const float* x   = (const float*)d_in[0];
    const float* ea  = (const float*)d_in[1];
    const void*  idx = d_in[2];
    const float* W   = (const float*)d_in[3];
    const float* b   = (const float*)d_in[4];
    float* out = (float*)d_out;

    int E = in_sizes[1] / 64;                  // edge_attr is [E, 64]
    int ntiles = (E + TILE_M - 1) / TILE_M;

    int dev = 0, sms = 148;
    cudaGetDevice(&dev);
    cudaDeviceGetAttribute(&sms, cudaDevAttrMultiProcessorCount, dev);

    size_t smem = (size_t)(2 * TILE_M * LDA + 128 * LDA + 128) * sizeof(float);
    cudaFuncSetAttribute(edge_encoder_kernel,
                         cudaFuncAttributeMaxDynamicSharedMemorySize, (int)smem);

    detect_idx_kernel<<<1, 32>>>((const unsigned int*)idx);

    int grid = sms < ntiles ? sms : ntiles;
    edge_encoder_kernel<<<grid, NTHREADS, smem>>>(x, ea, idx, W, b, out, E, ntiles);
}

// round 6
// speedup vs baseline: 1.0280x; 1.0280x over previous
#include <cuda_runtime.h>
#include <cstdint>

#define TILE_M   128
#define LDA      132          // 128 + 4 floats pad -> conflict-free fragment LDS
#define NTHREADS 512

__device__ int g_idx_is64;

// Index dtype sniffing: int64 indices (< 2^31, non-negative) have all-zero high
// words; int32 data at odd word positions is ~never all-zero for 64 samples.
__global__ void detect_idx_kernel(const unsigned int* __restrict__ w) {
    if (threadIdx.x == 0) {
        int is64 = 1;
        for (int i = 0; i < 64; i++)
            if (w[2 * i + 1] != 0u) { is64 = 0; break; }
        g_idx_is64 = is64;
    }
}

__device__ __forceinline__ void cp16(float* dst, const float* src) {
    uint32_t d = (uint32_t)__cvta_generic_to_shared(dst);
    asm volatile("cp.async.cg.shared.global [%0], [%1], 16;\n" :: "r"(d), "l"(src));
}

__device__ __forceinline__ uint32_t f2tf32(float v) {
    uint32_t u;
    asm("cvt.rna.tf32.f32 %0, %1;" : "=r"(u) : "f"(v));
    return u;
}

__device__ __forceinline__ void mma_tf32(float c[4], uint32_t a0, uint32_t a1,
                                         uint32_t a2, uint32_t a3,
                                         uint32_t b0, uint32_t b1) {
    asm volatile(
        "mma.sync.aligned.m16n8k8.row.col.f32.tf32.tf32.f32 "
        "{%0,%1,%2,%3}, {%4,%5,%6,%7}, {%8,%9}, {%0,%1,%2,%3};\n"
        : "+f"(c[0]), "+f"(c[1]), "+f"(c[2]), "+f"(c[3])
        : "r"(a0), "r"(a1), "r"(a2), "r"(a3), "r"(b0), "r"(b1));
}

__global__ void __launch_bounds__(NTHREADS, 1)
edge_encoder_kernel(const float* __restrict__ x,
                    const float* __restrict__ ea,
                    const void* __restrict__ idx,
                    const float* __restrict__ Wg,
                    const float* __restrict__ bg,
                    float* __restrict__ out,
                    int E, int ntiles) {
    extern __shared__ float smem[];
    float* As = smem;                       // 2 stages * 128 * LDA
    float* Ws = smem + 2 * TILE_M * LDA;    // 128 * LDA  (TF32-rounded W, [n][k])
    float* Bs = Ws + 128 * LDA;             // 128 bias

    const int tid  = threadIdx.x;
    const int lane = tid & 31;
    const int warp = tid >> 5;
    const int g    = lane >> 2;   // groupID 0..7
    const int tig  = lane & 3;    // thread-in-group 0..3
    const int wm   = warp >> 2;   // 0..3  (32-row slab)
    const int wn   = warp & 3;    // 0..3  (32-col slab)
    const int is64 = g_idx_is64;

    // Stage W (pre-rounded to TF32, [n][k] with LDA pad) and bias once per CTA.
    for (int i = tid; i < 128 * 128; i += NTHREADS) {
        int r = i >> 7, c = i & 127;
        Ws[r * LDA + c] = __uint_as_float(f2tf32(Wg[i]));
    }
    if (tid < 128) Bs[tid] = bg[tid];

    // Gather: 4 threads per edge-row. qtr 0,1 -> x[row[e]] (32+32 floats),
    // qtr 2,3 -> edge_attr[e] (32+32 floats). 8 cp.async(16B) per thread.
    const int rowi = tid >> 2;
    const int qtr  = tid & 3;
    const int half = qtr >> 1;    // 0 = x, 1 = edge_attr
    const int sub  = qtr & 1;     // which 32-float half of the 64
    auto issue = [&](int stage, long tile) {
        long e  = tile * TILE_M + rowi;
        long ec = e < E ? e : (long)(E - 1);
        const float* src;
        if (half == 0) {
            long r = is64 ? (long)((const long long*)idx)[ec]
                          : (long)((const int*)idx)[ec];
            src = x + (r << 6);
        } else {
            src = ea + (ec << 6);
        }
        src += sub * 32;
        float* dst = As + stage * (TILE_M * LDA) + rowi * LDA + half * 64 + sub * 32;
        #pragma unroll
        for (int q = 0; q < 8; q++) cp16(dst + q * 4, src + q * 4);
    };

    long tile0 = blockIdx.x;
    if (tile0 < ntiles) issue(0, tile0);
    asm volatile("cp.async.commit_group;\n");
    __syncthreads();   // Ws / Bs visible

    // Hoisted bias (cols wn*32 + nn*8 + 2*tig)
    float2 bb[4];
    #pragma unroll
    for (int nn = 0; nn < 4; nn++) {
        int col = wn * 32 + nn * 8 + 2 * tig;
        bb[nn] = make_float2(Bs[col], Bs[col + 1]);
    }

    int s = 0;
    for (long tile = tile0; tile < ntiles; tile += gridDim.x, s ^= 1) {
        long nxt = tile + gridDim.x;
        if (nxt < ntiles) issue(s ^ 1, nxt);
        asm volatile("cp.async.commit_group;\n");
        asm volatile("cp.async.wait_group 1;\n");   // current stage landed
        __syncthreads();

        const float* A0 = As + s * (TILE_M * LDA);

        float c[2][4][4];   // [m16-block][n8-block][frag]
        #pragma unroll
        for (int mb = 0; mb < 2; mb++)
            #pragma unroll
            for (int nn = 0; nn < 4; nn++)
                #pragma unroll
                for (int q = 0; q < 4; q++) c[mb][nn][q] = 0.f;

        const float* Ap = A0 + (wm * 32 + g) * LDA + tig;
        const float* Bp = Ws + (wn * 32 + g) * LDA + tig;

        #pragma unroll
        for (int ks = 0; ks < 16; ks++) {
            uint32_t a[2][4];
            #pragma unroll
            for (int mb = 0; mb < 2; mb++) {
                const float* ap = Ap + mb * 16 * LDA + ks * 8;
                a[mb][0] = f2tf32(ap[0]);
                a[mb][1] = f2tf32(ap[8 * LDA]);
                a[mb][2] = f2tf32(ap[4]);
                a[mb][3] = f2tf32(ap[8 * LDA + 4]);
            }
            uint32_t bf[4][2];
            #pragma unroll
            for (int nn = 0; nn < 4; nn++) {
                const float* bp = Bp + nn * 8 * LDA + ks * 8;
                bf[nn][0] = __float_as_uint(bp[0]);
                bf[nn][1] = __float_as_uint(bp[4]);
            }
            #pragma unroll
            for (int mb = 0; mb < 2; mb++)
                #pragma unroll
                for (int nn = 0; nn < 4; nn++)
                    mma_tf32(c[mb][nn], a[mb][0], a[mb][1], a[mb][2], a[mb][3],
                             bf[nn][0], bf[nn][1]);
        }

        // Epilogue: bias + relu + float2 stores.
        #pragma unroll
        for (int mb = 0; mb < 2; mb++) {
            long e0 = tile * TILE_M + wm * 32 + mb * 16 + g;
            #pragma unroll
            for (int hh = 0; hh < 2; hh++) {
                long e = e0 + hh * 8;
                if (e < E) {
                    float* orow = out + e * 128 + wn * 32 + 2 * tig;
                    #pragma unroll
                    for (int nn = 0; nn < 4; nn++) {
                        float v0 = fmaxf(c[mb][nn][2 * hh + 0] + bb[nn].x, 0.f);
                        float v1 = fmaxf(c[mb][nn][2 * hh + 1] + bb[nn].y, 0.f);
                        *(float2*)(orow + nn * 8) = make_float2(v0, v1);
                    }
                }
            }
        }
        __syncthreads();  // protect stage s before refill next iteration
    }
}

extern "C" void kernel_launch(void* const* d_in, const int* in_sizes, int n_in,
                              void* d_out, int out_size) {
    const float* x   = (const float*)d_in[0];
    const float* ea  = (const float*)d_in[1];
    const void*  idx = d_in[2];
    const float* W   = (const float*)d_in[3];
    const float* b   = (const float*)d_in[4];
    float* out = (float*)d_out;

    int E = in_sizes[1] / 64;                  // edge_attr is [E, 64]
    int ntiles = (E + TILE_M - 1) / TILE_M;

    int dev = 0, sms = 148;
    cudaGetDevice(&dev);
    cudaDeviceGetAttribute(&sms, cudaDevAttrMultiProcessorCount, dev);

    size_t smem = (size_t)(2 * TILE_M * LDA + 128 * LDA + 128) * sizeof(float);
    cudaFuncSetAttribute(edge_encoder_kernel,
                         cudaFuncAttributeMaxDynamicSharedMemorySize, (int)smem);

    detect_idx_kernel<<<1, 32>>>((const unsigned int*)idx);

    int grid = sms < ntiles ? sms : ntiles;
    edge_encoder_kernel<<<grid, NTHREADS, smem>>>(x, ea, idx, W, b, out, E, ntiles);
}

// round 8
// speedup vs baseline: 1.2331x; 1.1996x over previous
#include <cuda_runtime.h>
#include <cuda_fp16.h>
#include <cstdint>

#define TILE_M   128
#define NTHREADS 512

// ---- SMEM layout (bytes) ----
#define SM_A0    0          // 2 stages x 128 rows x 128 fp16 (swizzled 16B chunks)
#define SM_AST   32768
#define SM_W     65536      // 128 x 128 fp16, same swizzled layout, [n][k]
#define SM_BIAS  98304      // 128 f32
#define SM_TOT   98816

__device__ int g_idx_is64;

// Index dtype sniffing: int64 indices (< 2^31, non-negative) have all-zero high
// words; int32 data at odd word positions is ~never all-zero for 64 samples.
__global__ void detect_idx_kernel(const unsigned int* __restrict__ w) {
    if (threadIdx.x == 0) {
        int is64 = 1;
        for (int i = 0; i < 64; i++)
            if (w[2 * i + 1] != 0u) { is64 = 0; break; }
        g_idx_is64 = is64;
    }
}

__device__ __forceinline__ uint32_t smem_u32(const void* p) {
    return (uint32_t)__cvta_generic_to_shared(p);
}
// swizzled byte offset of 16B chunk `chunk` in row `row` (256B rows)
__device__ __forceinline__ uint32_t sw(int row, int chunk) {
    return (uint32_t)((row << 8) + ((chunk ^ (row & 7)) << 4));
}
__device__ __forceinline__ uint32_t f2h2(float a, float b) {
    __half2 h = __floats2half2_rn(a, b);
    return *reinterpret_cast<uint32_t*>(&h);
}
__device__ __forceinline__ void ldsm4(uint32_t r[4], uint32_t addr) {
    asm volatile("ldmatrix.sync.aligned.m8n8.x4.shared.b16 {%0,%1,%2,%3}, [%4];"
                 : "=r"(r[0]), "=r"(r[1]), "=r"(r[2]), "=r"(r[3]) : "r"(addr));
}
__device__ __forceinline__ void mma_f16(float c[4], const uint32_t a[4],
                                        uint32_t b0, uint32_t b1) {
    asm volatile(
        "mma.sync.aligned.m16n8k16.row.col.f32.f16.f16.f32 "
        "{%0,%1,%2,%3}, {%4,%5,%6,%7}, {%8,%9}, {%0,%1,%2,%3};\n"
        : "+f"(c[0]), "+f"(c[1]), "+f"(c[2]), "+f"(c[3])
        : "r"(a[0]), "r"(a[1]), "r"(a[2]), "r"(a[3]), "r"(b0), "r"(b1));
}

__global__ void __launch_bounds__(NTHREADS, 1)
edge_encoder_kernel(const float* __restrict__ x,
                    const float* __restrict__ ea,
                    const void* __restrict__ idx,
                    const float* __restrict__ Wg,
                    const float* __restrict__ bg,
                    float* __restrict__ out,
                    int E, int ntiles) {
    extern __shared__ char smem[];
    const uint32_t sb = smem_u32(smem);
    const int tid  = threadIdx.x;
    const int lane = tid & 31;
    const int warp = tid >> 5;
    const int g    = lane >> 2;
    const int tig  = lane & 3;
    const int wm   = warp >> 2;   // 0..3 (32-row slab)
    const int wn   = warp & 3;    // 0..3 (32-col slab)
    const int is64 = g_idx_is64;

    // ---- stage W as fp16 (RN) into swizzled [n][k] layout, plus bias ----
    for (int p = tid; p < 8192; p += NTHREADS) {     // 8192 half2 pairs
        int n = p >> 6, kp = p & 63;                 // k = 2*kp
        float2 w2 = *(const float2*)&Wg[n * 128 + 2 * kp];
        *(uint32_t*)(smem + SM_W + sw(n, kp >> 2) + (kp & 3) * 4) = f2h2(w2.x, w2.y);
    }
    float* Bs = (float*)(smem + SM_BIAS);
    if (tid < 128) Bs[tid] = bg[tid];

    // ---- gather mapping: 4 threads per edge-row ----
    const int rowi = tid >> 2;
    const int qtr  = tid & 3;
    const int half = qtr >> 1;    // 0 = x[row[e]], 1 = edge_attr[e]
    const int sub  = qtr & 1;     // 32-float half within the 64

    auto loadIdx = [&](long tile) -> long {
        if (half != 0) return 0;
        long e  = tile * TILE_M + rowi;
        long ec = e < (long)E ? e : (long)(E - 1);
        return is64 ? (long)((const long long*)idx)[ec]
                    : (long)((const int*)idx)[ec];
    };
    auto issueLDG = [&](float4 gb[8], long r, long tile) {
        long e  = tile * TILE_M + rowi;
        long ec = e < (long)E ? e : (long)(E - 1);
        const float* src = (half == 0) ? (x + (r << 6)) : (ea + (ec << 6));
        src += sub * 32;
        #pragma unroll
        for (int q = 0; q < 8; q++) gb[q] = *(const float4*)(src + 4 * q);
    };
    auto cvtSTS = [&](const float4 gb[8], int stage) {
        #pragma unroll
        for (int j = 0; j < 4; j++) {
            uint4 o;
            o.x = f2h2(gb[2 * j].x,     gb[2 * j].y);
            o.y = f2h2(gb[2 * j].z,     gb[2 * j].w);
            o.z = f2h2(gb[2 * j + 1].x, gb[2 * j + 1].y);
            o.w = f2h2(gb[2 * j + 1].z, gb[2 * j + 1].w);
            *(uint4*)(smem + SM_A0 + stage * SM_AST + sw(rowi, qtr * 4 + j)) = o;
        }
    };

    const long stride = gridDim.x;
    const long tile0  = blockIdx.x;

    // prologue: gather tile0 into stage 0; prefetch idx for tile0+stride
    {
        long r0 = loadIdx(tile0);
        float4 gb[8];
        issueLDG(gb, r0, tile0);
        cvtSTS(gb, 0);
    }
    long riCur = loadIdx(tile0 + stride);
    __syncthreads();

    // hoisted bias (cols wn*32 + nn*8 + 2*tig)
    float2 bb[4];
    #pragma unroll
    for (int nn = 0; nn < 4; nn++) {
        int col = wn * 32 + nn * 8 + 2 * tig;
        bb[nn] = make_float2(Bs[col], Bs[col + 1]);
    }

    // per-warp ldmatrix lane terms
    const int r7  = lane & 7;
    const int hiA = lane >> 4;                      // 0/1
    const int hiB = (lane >> 3) & 1;                // 0/1
    const uint32_t aRowOff = (uint32_t)((wm * 32 + (lane & 15)) << 8);
    const uint32_t bBase0  = sb + SM_W +
        (uint32_t)((wn * 32 + (lane & 7) + ((lane >> 4) << 3)) << 8);
    const uint32_t bBase1  = bBase0 + (16 << 8);

    int s = 0;
    for (long tile = tile0; tile < ntiles; tile += stride, s ^= 1) {
        long next = tile + stride;
        const bool hasNext = next < ntiles;
        float4 gb[8];
        if (hasNext) {
            issueLDG(gb, riCur, next);              // latency hidden by compute
            riCur = loadIdx(next + stride);         // idx prefetch for next iter
        }

        const uint32_t aBase = sb + SM_A0 + s * SM_AST + aRowOff;

        float c[2][4][4];
        #pragma unroll
        for (int mb = 0; mb < 2; mb++)
            #pragma unroll
            for (int nn = 0; nn < 4; nn++)
                #pragma unroll
                for (int q = 0; q < 4; q++) c[mb][nn][q] = 0.f;

        #pragma unroll
        for (int ks = 0; ks < 8; ks++) {
            uint32_t a0[4], a1[4], b0[4], b1[4];
            uint32_t ca = (uint32_t)(((2 * ks + hiA) ^ r7) << 4);
            uint32_t cb = (uint32_t)(((2 * ks + hiB) ^ r7) << 4);
            ldsm4(a0, aBase + ca);
            ldsm4(a1, aBase + (16 << 8) + ca);
            ldsm4(b0, bBase0 + cb);
            ldsm4(b1, bBase1 + cb);
            mma_f16(c[0][0], a0, b0[0], b0[1]);
            mma_f16(c[0][1], a0, b0[2], b0[3]);
            mma_f16(c[0][2], a0, b1[0], b1[1]);
            mma_f16(c[0][3], a0, b1[2], b1[3]);
            mma_f16(c[1][0], a1, b0[0], b0[1]);
            mma_f16(c[1][1], a1, b0[2], b0[3]);
            mma_f16(c[1][2], a1, b1[0], b1[1]);
            mma_f16(c[1][3], a1, b1[2], b1[3]);
        }

        // write next A stage early so STS drain overlaps epilogue STGs
        if (hasNext) cvtSTS(gb, s ^ 1);

        // epilogue: bias + relu + float2 stores
        #pragma unroll
        for (int mb = 0; mb < 2; mb++) {
            long e0 = tile * TILE_M + wm * 32 + mb * 16 + g;
            #pragma unroll
            for (int hh = 0; hh < 2; hh++) {
                long e = e0 + hh * 8;
                if (e < E) {
                    float* orow = out + e * 128 + wn * 32 + 2 * tig;
                    #pragma unroll
                    for (int nn = 0; nn < 4; nn++) {
                        float v0 = fmaxf(c[mb][nn][2 * hh + 0] + bb[nn].x, 0.f);
                        float v1 = fmaxf(c[mb][nn][2 * hh + 1] + bb[nn].y, 0.f);
                        *(float2*)(orow + nn * 8) = make_float2(v0, v1);
                    }
                }
            }
        }
        __syncthreads();   // stage s^1 visible; stage s free for refill
    }
}

extern "C" void kernel_launch(void* const* d_in, const int* in_sizes, int n_in,
                              void* d_out, int out_size) {
    const float* x   = (const float*)d_in[0];
    const float* ea  = (const float*)d_in[1];
    const void*  idx = d_in[2];
    const float* W   = (const float*)d_in[3];
    const float* b   = (const float*)d_in[4];
    float* out = (float*)d_out;

    int E = in_sizes[1] / 64;                  // edge_attr is [E, 64]
    int ntiles = (E + TILE_M - 1) / TILE_M;

    int dev = 0, sms = 148;
    cudaGetDevice(&dev);
    cudaDeviceGetAttribute(&sms, cudaDevAttrMultiProcessorCount, dev);

    cudaFuncSetAttribute(edge_encoder_kernel,
                         cudaFuncAttributeMaxDynamicSharedMemorySize, SM_TOT);

    detect_idx_kernel<<<1, 32>>>((const unsigned int*)idx);

    int grid = sms < ntiles ? sms : ntiles;
    edge_encoder_kernel<<<grid, NTHREADS, SM_TOT>>>(x, ea, idx, W, b, out, E, ntiles);
}